// round 11
// baseline (speedup 1.0000x reference)
#include <cuda_runtime.h>

#define NMAX 50000
#define EMAX 800000
#define HC   128
#define FIN  64

// ---------------- scratch (static device arrays; no allocation) ----------------
__device__ float h_g[NMAX * HC];        // x @ W                [N,128]
__device__ float res_g[NMAX * HC];      // x @ res_w + res_b    [N,128]
__device__ float a_src_g[NMAX * 4];     // per-head src coeff   [N,4]
__device__ float a_dst_g[NMAX * 4];     // per-head dst coeff   [N,4]
__device__ int   deg_g[NMAX];           // zero at load; scan re-zeros after use
__device__ int   rowptr_g[NMAX + 1];
__device__ int   rowcur_g[NMAX];
__device__ int   col_g[EMAX];
__device__ int   src_g[EMAX];
__device__ int   dst_g[EMAX];

#define LEAKY(v) ((v) >= 0.f ? (v) : 0.2f * (v))

// ---------------- extract src/dst + histogram (detection folded in) -----------
__global__ void extract_hist_kernel(const void* __restrict__ raw, int E)
{
    __shared__ int s_has_nonzero_odd;
    const int* p32 = (const int*)raw;

    if (threadIdx.x == 0) s_has_nonzero_odd = 0;
    __syncthreads();
    int nwords = 1024;
    if (nwords > 2 * E) nwords = 2 * E;
    int nz = 0;
    for (int j = threadIdx.x; j < nwords / 2; j += blockDim.x)
        nz |= p32[2 * j + 1];
    if (nz) atomicOr(&s_has_nonzero_odd, 1);
    __syncthreads();
    int is64 = !s_has_nonzero_odd;

    int i = blockIdx.x * blockDim.x + threadIdx.x;
    if (i >= E) return;
    int s, d;
    if (is64) {
        const long long* p = (const long long*)raw;
        s = (int)p[i];
        d = (int)p[E + i];
    } else {
        s = p32[i];
        d = p32[E + i];
    }
    src_g[i] = s;
    dst_g[i] = d;
    atomicAdd(&deg_g[d], 1);
}

// ---------------- single-block scan over N (re-zeros deg for next launch) -----
__global__ void scan_kernel(int n)
{
    __shared__ int sh[1024];
    int t = threadIdx.x;
    int chunk = (n + 1023) >> 10;
    int s0 = t * chunk;
    int s1 = s0 + chunk;
    if (s0 > n) s0 = n;
    if (s1 > n) s1 = n;
    int s = 0;
#pragma unroll 4
    for (int i = s0; i < s1; i++) s += deg_g[i];
    sh[t] = s;
    __syncthreads();
#pragma unroll
    for (int off = 1; off < 1024; off <<= 1) {
        int v = (t >= off) ? sh[t - off] : 0;
        __syncthreads();
        sh[t] += v;
        __syncthreads();
    }
    int run = sh[t] - s;  // exclusive prefix
    for (int i = s0; i < s1; i++) {
        int d = deg_g[i];
        rowptr_g[i] = run;
        rowcur_g[i] = run;
        deg_g[i] = 0;       // leave zeroed for the next launch (graph replay)
        run += d;
    }
    if (t == 1023) rowptr_g[n] = sh[1023];
}

__global__ void scatter_kernel(int E)
{
    int i = blockIdx.x * blockDim.x + threadIdx.x;
    if (i >= E) return;
    int p = atomicAdd(&rowcur_g[dst_g[i]], 1);
    col_g[p] = src_g[i];
}

// ---------------- fused GEMM: h = x@W ; res = x@res_w + res_b ; att coeffs ----
// 256 threads. Warp lanes = 32 nodes; warp w covers cols [w*32, w*32+32).
// x streamed per-lane from global (L2-resident) -> no xsh, no per-tile syncs.
// smem = Wsh 64KB + att 1KB -> 3 blocks/SM (vs 2 with xsh).
__global__ void gemm_kernel(const float* __restrict__ x, const float* __restrict__ W,
                            const float* __restrict__ Rw, const float* __restrict__ Rb,
                            const float* __restrict__ att_s, const float* __restrict__ att_d,
                            int n, int ntiles)
{
    extern __shared__ float smem[];
    float* Wsh = smem;                     // [64][256]
    float* asl = smem + FIN * 256;         // [128] att_src
    float* adl = asl + 128;                // [128] att_dst

    int t = threadIdx.x;
    for (int i = t; i < FIN * 256; i += 256) {
        int c = i & 255;
        int k = i >> 8;
        Wsh[i] = (c < 128) ? W[k * 128 + c] : Rw[k * 128 + (c - 128)];
    }
    if (t < 128) {
        asl[t] = att_s[t];
        adl[t] = att_d[t];
    }
    __syncthreads();   // once; tiles below run sync-free

    int lane = t & 31, wid = t >> 5;

    for (int tile = blockIdx.x; tile < ntiles; tile += gridDim.x) {
        int node = (tile << 5) + lane;
        int nclamp = node < n ? node : n - 1;          // in-bounds read, store guarded
        const float4* xr = (const float4*)(x + (size_t)nclamp * FIN);

        float acc[32];
#pragma unroll
        for (int q = 0; q < 32; q++) acc[q] = 0.f;

#pragma unroll 2
        for (int kc = 0; kc < FIN / 4; kc++) {
            float4 xv4 = xr[kc];
#pragma unroll
            for (int j = 0; j < 4; j++) {
                float xv = j == 0 ? xv4.x : j == 1 ? xv4.y : j == 2 ? xv4.z : xv4.w;
                const float4* wrow = (const float4*)&Wsh[(kc * 4 + j) * 256 + wid * 32];
#pragma unroll
                for (int q = 0; q < 8; q++) {
                    float4 wv = wrow[q];
                    acc[q * 4 + 0] += xv * wv.x;
                    acc[q * 4 + 1] += xv * wv.y;
                    acc[q * 4 + 2] += xv * wv.z;
                    acc[q * 4 + 3] += xv * wv.w;
                }
            }
        }

        if (node < n) {
            if (wid < 4) {
                float4* hp = (float4*)&h_g[node * HC + wid * 32];
#pragma unroll
                for (int q = 0; q < 8; q++)
                    hp[q] = make_float4(acc[q * 4], acc[q * 4 + 1], acc[q * 4 + 2], acc[q * 4 + 3]);
                // attention dots for head = wid (broadcast smem reads)
                float ss = 0.f, sd = 0.f;
#pragma unroll
                for (int c = 0; c < 32; c++) {
                    ss += acc[c] * asl[wid * 32 + c];
                    sd += acc[c] * adl[wid * 32 + c];
                }
                a_src_g[node * 4 + wid] = ss;
                a_dst_g[node * 4 + wid] = sd;
            } else {
                int c0 = (wid - 4) * 32;
                float4* rp = (float4*)&res_g[node * HC + c0];
                const float4* bp = (const float4*)&Rb[c0];
#pragma unroll
                for (int q = 0; q < 8; q++) {
                    float4 b = bp[q];
                    rp[q] = make_float4(acc[q * 4] + b.x, acc[q * 4 + 1] + b.y,
                                        acc[q * 4 + 2] + b.z, acc[q * 4 + 3] + b.w);
                }
            }
        }
    }
}

// ---------------- fused aggregate + softmax + ELU + residual + LayerNorm ------
// One warp per destination node (round-3 proven form). Lane l holds channels
// [4l,4l+4), head = l/8. No max subtraction (exp safe in fp32).
__global__ void aggregate_kernel(const float* __restrict__ bias,
                                 const float* __restrict__ lng, const float* __restrict__ lnb,
                                 float* __restrict__ out, int n)
{
    int warp = (blockIdx.x * blockDim.x + threadIdx.x) >> 5;
    int lane = threadIdx.x & 31;
    if (warp >= n) return;
    int v = warp;
    int head = lane >> 3;

    float adh = a_dst_g[v * 4 + head];
    const float4* hp = (const float4*)h_g;

    // self loop
    float w0 = __expf(LEAKY(a_src_g[v * 4 + head] + adh));
    float4 hv = hp[v * 32 + lane];
    float4 acc = make_float4(w0 * hv.x, w0 * hv.y, w0 * hv.z, w0 * hv.w);
    float dsum = w0;

    int rs = rowptr_g[v], re = rowptr_g[v + 1];
    int i = rs;
    // 4x unrolled: batch index loads -> batch coeff loads -> batch row loads
    for (; i + 4 <= re; i += 4) {
        int u0 = col_g[i], u1 = col_g[i + 1], u2 = col_g[i + 2], u3 = col_g[i + 3];
        float e0 = a_src_g[u0 * 4 + head];
        float e1 = a_src_g[u1 * 4 + head];
        float e2 = a_src_g[u2 * 4 + head];
        float e3 = a_src_g[u3 * 4 + head];
        float4 h0 = hp[u0 * 32 + lane];
        float4 h1 = hp[u1 * 32 + lane];
        float4 h2 = hp[u2 * 32 + lane];
        float4 h3 = hp[u3 * 32 + lane];
        float x0 = __expf(LEAKY(e0 + adh));
        float x1 = __expf(LEAKY(e1 + adh));
        float x2 = __expf(LEAKY(e2 + adh));
        float x3 = __expf(LEAKY(e3 + adh));
        acc.x += x0 * h0.x + x1 * h1.x + x2 * h2.x + x3 * h3.x;
        acc.y += x0 * h0.y + x1 * h1.y + x2 * h2.y + x3 * h3.y;
        acc.z += x0 * h0.z + x1 * h1.z + x2 * h2.z + x3 * h3.z;
        acc.w += x0 * h0.w + x1 * h1.w + x2 * h2.w + x3 * h3.w;
        dsum += x0 + x1 + x2 + x3;
    }
    for (; i < re; i++) {
        int u = col_g[i];
        float wv = __expf(LEAKY(a_src_g[u * 4 + head] + adh));
        float4 hu = hp[u * 32 + lane];
        acc.x += wv * hu.x;
        acc.y += wv * hu.y;
        acc.z += wv * hu.z;
        acc.w += wv * hu.w;
        dsum += wv;
    }

    float inv = 1.f / dsum;
    float4 b = ((const float4*)bias)[lane];
    float4 o;
    o.x = acc.x * inv + b.x;
    o.y = acc.y * inv + b.y;
    o.z = acc.z * inv + b.z;
    o.w = acc.w * inv + b.w;

    // ELU
    o.x = o.x > 0.f ? o.x : expm1f(o.x);
    o.y = o.y > 0.f ? o.y : expm1f(o.y);
    o.z = o.z > 0.f ? o.z : expm1f(o.z);
    o.w = o.w > 0.f ? o.w : expm1f(o.w);

    // residual
    float4 r = ((const float4*)res_g)[v * 32 + lane];
    o.x += r.x; o.y += r.y; o.z += r.z; o.w += r.w;

    // LayerNorm over 128 (warp-wide)
    float s = o.x + o.y + o.z + o.w;
#pragma unroll
    for (int off = 16; off; off >>= 1) s += __shfl_xor_sync(0xffffffffu, s, off);
    float mean = s * (1.f / 128.f);

    float cx = o.x - mean, cy = o.y - mean, cz = o.z - mean, cw = o.w - mean;
    float sq = cx * cx + cy * cy + cz * cz + cw * cw;
#pragma unroll
    for (int off = 16; off; off >>= 1) sq += __shfl_xor_sync(0xffffffffu, sq, off);
    float rinv = rsqrtf(sq * (1.f / 128.f) + 1e-5f);

    float4 g  = ((const float4*)lng)[lane];
    float4 lb = ((const float4*)lnb)[lane];
    float4 oo;
    oo.x = cx * rinv * g.x + lb.x;
    oo.y = cy * rinv * g.y + lb.y;
    oo.z = cz * rinv * g.z + lb.z;
    oo.w = cw * rinv * g.w + lb.w;

    ((float4*)out)[v * 32 + lane] = oo;
}

// ---------------- launch (fork-join; gemm is 4th submission -> ncu target) ----
extern "C" void kernel_launch(void* const* d_in, const int* in_sizes, int n_in,
                              void* d_out, int out_size)
{
    const float* x     = (const float*)d_in[0];
    const void*  ei    = d_in[1];
    const float* W     = (const float*)d_in[2];
    const float* att_s = (const float*)d_in[3];
    const float* att_d = (const float*)d_in[4];
    const float* bias  = (const float*)d_in[5];
    const float* Rw    = (const float*)d_in[6];
    const float* Rb    = (const float*)d_in[7];
    const float* lng   = (const float*)d_in[8];
    const float* lnb   = (const float*)d_in[9];

    int n = in_sizes[0] / FIN;
    int E = in_sizes[1] / 2;
    int ntiles = (n + 31) / 32;

    static cudaStream_t s2 = 0;
    static cudaEvent_t evFork = 0, evJoin = 0;
    static int inited = 0;
    int gemm_smem = (FIN * 256 + 256) * (int)sizeof(float);   // 66.6KB -> 3 blocks/SM
    if (!inited) {
        cudaFuncSetAttribute(gemm_kernel, cudaFuncAttributeMaxDynamicSharedMemorySize, gemm_smem);
        cudaStreamCreateWithFlags(&s2, cudaStreamNonBlocking);
        cudaEventCreateWithFlags(&evFork, cudaEventDisableTiming);
        cudaEventCreateWithFlags(&evJoin, cudaEventDisableTiming);
        inited = 1;
    }

    // fork: s2 does the CSR build while stream 0 does the GEMM
    cudaEventRecord(evFork, 0);
    cudaStreamWaitEvent(s2, evFork, 0);

    extract_hist_kernel<<<(E + 255) / 256, 256, 0, s2>>>(ei, E);   // submission 1
    scan_kernel<<<1, 1024, 0, s2>>>(n);                            // submission 2
    scatter_kernel<<<(E + 255) / 256, 256, 0, s2>>>(E);            // submission 3
    cudaEventRecord(evJoin, s2);

    gemm_kernel<<<444, 256, gemm_smem>>>(x, W, Rw, Rb, att_s, att_d, n, ntiles);  // submission 4 (profiled)

    // join
    cudaStreamWaitEvent(0, evJoin, 0);
    aggregate_kernel<<<(n + 7) / 8, 256>>>(bias, lng, lnb, (float*)d_out, n);     // submission 5
}

// round 12
// speedup vs baseline: 1.0135x; 1.0135x over previous
#include <cuda_runtime.h>
#include <cuda_fp16.h>

#define NMAX 50000
#define EMAX 800000
#define HC   128
#define FIN  64

// ---------------- scratch (static device arrays; no allocation) ----------------
__device__ float h_g[NMAX * HC];        // x @ W                [N,128]
__device__ float res_g[NMAX * HC];      // x @ res_w + res_b    [N,128]
__device__ float a_src_g[NMAX * 4];     // per-head src coeff   [N,4]
__device__ float a_dst_g[NMAX * 4];     // per-head dst coeff   [N,4]
__device__ int   deg_g[NMAX];           // zero at load; scan re-zeros after use
__device__ int   rowptr_g[NMAX + 1];
__device__ int   rowcur_g[NMAX];
__device__ int   col_g[EMAX];
__device__ int   src_g[EMAX];
__device__ int   dst_g[EMAX];

#define LEAKY(v) ((v) >= 0.f ? (v) : 0.2f * (v))

// ---------------- extract src/dst + histogram (detection folded in) -----------
__global__ void extract_hist_kernel(const void* __restrict__ raw, int E)
{
    __shared__ int s_has_nonzero_odd;
    const int* p32 = (const int*)raw;

    if (threadIdx.x == 0) s_has_nonzero_odd = 0;
    __syncthreads();
    int nwords = 1024;
    if (nwords > 2 * E) nwords = 2 * E;
    int nz = 0;
    for (int j = threadIdx.x; j < nwords / 2; j += blockDim.x)
        nz |= p32[2 * j + 1];
    if (nz) atomicOr(&s_has_nonzero_odd, 1);
    __syncthreads();
    int is64 = !s_has_nonzero_odd;

    int i = blockIdx.x * blockDim.x + threadIdx.x;
    if (i >= E) return;
    int s, d;
    if (is64) {
        const long long* p = (const long long*)raw;
        s = (int)p[i];
        d = (int)p[E + i];
    } else {
        s = p32[i];
        d = p32[E + i];
    }
    src_g[i] = s;
    dst_g[i] = d;
    atomicAdd(&deg_g[d], 1);
}

// ---------------- single-block scan over N (re-zeros deg for next launch) -----
__global__ void scan_kernel(int n)
{
    __shared__ int sh[1024];
    int t = threadIdx.x;
    int chunk = (n + 1023) >> 10;
    int s0 = t * chunk;
    int s1 = s0 + chunk;
    if (s0 > n) s0 = n;
    if (s1 > n) s1 = n;
    int s = 0;
#pragma unroll 4
    for (int i = s0; i < s1; i++) s += deg_g[i];
    sh[t] = s;
    __syncthreads();
#pragma unroll
    for (int off = 1; off < 1024; off <<= 1) {
        int v = (t >= off) ? sh[t - off] : 0;
        __syncthreads();
        sh[t] += v;
        __syncthreads();
    }
    int run = sh[t] - s;  // exclusive prefix
    for (int i = s0; i < s1; i++) {
        int d = deg_g[i];
        rowptr_g[i] = run;
        rowcur_g[i] = run;
        deg_g[i] = 0;       // leave zeroed for the next launch (graph replay)
        run += d;
    }
    if (t == 1023) rowptr_g[n] = sh[1023];
}

__global__ void scatter_kernel(int E)
{
    int i = blockIdx.x * blockDim.x + threadIdx.x;
    if (i >= E) return;
    int p = atomicAdd(&rowcur_g[dst_g[i]], 1);
    col_g[p] = src_g[i];
}

// ---------------- tensor-core GEMM: h = x@W ; res = x@res_w + b ; att dots ----
// mma.sync.m16n8k16 row.col, fp16 inputs, fp32 accum.
// Block 256 = 8 warps. Tile = 32 nodes x 256 cols; warp w: cols [w*32, w*32+32)
// (w<4 -> h + att dots for head w; w>=4 -> res + bias).
// Smem (words): Wsh 256x36 (n-major fp16, stride 72 halves), xsh 32x36,
// asl/adl/rbs 128 floats each. Stride 72 halves => conflict-free frag loads.
__device__ __forceinline__ void mma16816(float* c, const unsigned* a, const unsigned* b)
{
    asm volatile(
        "mma.sync.aligned.m16n8k16.row.col.f32.f16.f16.f32 "
        "{%0,%1,%2,%3}, {%4,%5,%6,%7}, {%8,%9}, {%0,%1,%2,%3};"
        : "+f"(c[0]), "+f"(c[1]), "+f"(c[2]), "+f"(c[3])
        : "r"(a[0]), "r"(a[1]), "r"(a[2]), "r"(a[3]), "r"(b[0]), "r"(b[1]));
}

#define W_WORDS (256 * 36)
#define X_WORDS (32 * 36)

__global__ void gemm_kernel(const float* __restrict__ x, const float* __restrict__ W,
                            const float* __restrict__ Rw, const float* __restrict__ Rb,
                            const float* __restrict__ att_s, const float* __restrict__ att_d,
                            int n, int ntiles)
{
    extern __shared__ unsigned smw[];
    unsigned* Wsh = smw;                       // fp16 n-major [col][k], stride 36 words
    unsigned* xsh = smw + W_WORDS;             // fp16 [node][k], stride 36 words
    float* asl = (float*)(smw + W_WORDS + X_WORDS);
    float* adl = asl + 128;
    float* rbs = adl + 128;

    int t = threadIdx.x;
    // convert W|Rw -> fp16 transposed (coalesced global reads)
    for (int idx = t; idx < FIN * 256; idx += 256) {
        int k = idx >> 8, c = idx & 255;
        float v = (c < 128) ? W[k * 128 + c] : Rw[k * 128 + (c - 128)];
        ((__half*)Wsh)[c * 72 + k] = __float2half(v);
    }
    if (t < 128) { asl[t] = att_s[t]; adl[t] = att_d[t]; rbs[t] = Rb[t]; }
    __syncthreads();

    int lane = t & 31, wid = t >> 5;
    int g = lane >> 2, qi = lane & 3;
    bool is_h = wid < 4;
    int colhalf = (wid & 3) * 32;              // col base within its 128-col half

    for (int tile = blockIdx.x; tile < ntiles; tile += gridDim.x) {
        int nb = tile << 5;
        // load + convert x tile: thread handles node r = t/8, k0 = (t%8)*8
        {
            int r = t >> 3, k0 = (t & 7) * 8;
            int node = nb + r;
            if (node >= n) node = n - 1;
            const float4* xr = (const float4*)(x + (size_t)node * FIN + k0);
            float4 v0 = xr[0], v1 = xr[1];
            __half2* dst = (__half2*)((__half*)xsh + r * 72 + k0);
            dst[0] = __floats2half2_rn(v0.x, v0.y);
            dst[1] = __floats2half2_rn(v0.z, v0.w);
            dst[2] = __floats2half2_rn(v1.x, v1.y);
            dst[3] = __floats2half2_rn(v1.z, v1.w);
        }
        __syncthreads();

        float acc[2][4][4];
#pragma unroll
        for (int nf = 0; nf < 2; nf++)
#pragma unroll
            for (int cf = 0; cf < 4; cf++)
#pragma unroll
                for (int q = 0; q < 4; q++) acc[nf][cf][q] = 0.f;

#pragma unroll
        for (int ks = 0; ks < 4; ks++) {
            int kw = ks * 8;                   // word offset of this k16 chunk
            unsigned a[2][4], b[4][2];
#pragma unroll
            for (int nf = 0; nf < 2; nf++) {
                unsigned base = (unsigned)(nf * 16 + g) * 36 + kw + qi;
                a[nf][0] = xsh[base];
                a[nf][1] = xsh[base + 8 * 36];
                a[nf][2] = xsh[base + 4];
                a[nf][3] = xsh[base + 4 + 8 * 36];
            }
#pragma unroll
            for (int cf = 0; cf < 4; cf++) {
                unsigned base = (unsigned)(wid * 32 + cf * 8 + g) * 36 + kw + qi;
                b[cf][0] = Wsh[base];
                b[cf][1] = Wsh[base + 4];
            }
#pragma unroll
            for (int nf = 0; nf < 2; nf++)
#pragma unroll
                for (int cf = 0; cf < 4; cf++)
                    mma16816(acc[nf][cf], a[nf], b[cf]);
        }
        __syncthreads();   // all mma reads done before next tile rewrites xsh

        // epilogue: stores + (h) att dots
        float* outb = is_h ? h_g : res_g;
#pragma unroll
        for (int nf = 0; nf < 2; nf++) {
            int node0 = nb + nf * 16 + g;
            int node1 = node0 + 8;
            float s0 = 0.f, d0 = 0.f, s1 = 0.f, d1 = 0.f;
#pragma unroll
            for (int cf = 0; cf < 4; cf++) {
                int c = colhalf + cf * 8 + qi * 2;     // within 128-col half
                float add0 = is_h ? 0.f : rbs[c];
                float add1 = is_h ? 0.f : rbs[c + 1];
                if (node0 < n) {
                    float2 v = make_float2(acc[nf][cf][0] + add0, acc[nf][cf][1] + add1);
                    *(float2*)&outb[(size_t)node0 * HC + c] = v;
                }
                if (node1 < n) {
                    float2 v = make_float2(acc[nf][cf][2] + add0, acc[nf][cf][3] + add1);
                    *(float2*)&outb[(size_t)node1 * HC + c] = v;
                }
                if (is_h) {
                    float as0 = asl[c], as1 = asl[c + 1];
                    float ad0 = adl[c], ad1 = adl[c + 1];
                    s0 += acc[nf][cf][0] * as0 + acc[nf][cf][1] * as1;
                    d0 += acc[nf][cf][0] * ad0 + acc[nf][cf][1] * ad1;
                    s1 += acc[nf][cf][2] * as0 + acc[nf][cf][3] * as1;
                    d1 += acc[nf][cf][2] * ad0 + acc[nf][cf][3] * ad1;
                }
            }
            if (is_h) {
#pragma unroll
                for (int off = 1; off < 4; off <<= 1) {
                    s0 += __shfl_xor_sync(0xffffffffu, s0, off);
                    d0 += __shfl_xor_sync(0xffffffffu, d0, off);
                    s1 += __shfl_xor_sync(0xffffffffu, s1, off);
                    d1 += __shfl_xor_sync(0xffffffffu, d1, off);
                }
                if (qi == 0) {
                    if (node0 < n) { a_src_g[node0 * 4 + wid] = s0; a_dst_g[node0 * 4 + wid] = d0; }
                    if (node1 < n) { a_src_g[node1 * 4 + wid] = s1; a_dst_g[node1 * 4 + wid] = d1; }
                }
            }
        }
    }
}

// ---------------- fused aggregate + softmax + ELU + residual + LayerNorm ------
// One warp per destination node. Lane l holds channels [4l,4l+4), head = l/8.
__global__ void aggregate_kernel(const float* __restrict__ bias,
                                 const float* __restrict__ lng, const float* __restrict__ lnb,
                                 float* __restrict__ out, int n)
{
    int warp = (blockIdx.x * blockDim.x + threadIdx.x) >> 5;
    int lane = threadIdx.x & 31;
    if (warp >= n) return;
    int v = warp;
    int head = lane >> 3;

    float adh = a_dst_g[v * 4 + head];
    const float4* hp = (const float4*)h_g;

    // self loop
    float w0 = __expf(LEAKY(a_src_g[v * 4 + head] + adh));
    float4 hv = hp[v * 32 + lane];
    float4 acc = make_float4(w0 * hv.x, w0 * hv.y, w0 * hv.z, w0 * hv.w);
    float dsum = w0;

    int rs = rowptr_g[v], re = rowptr_g[v + 1];
    int i = rs;
    for (; i + 4 <= re; i += 4) {
        int u0 = col_g[i], u1 = col_g[i + 1], u2 = col_g[i + 2], u3 = col_g[i + 3];
        float e0 = a_src_g[u0 * 4 + head];
        float e1 = a_src_g[u1 * 4 + head];
        float e2 = a_src_g[u2 * 4 + head];
        float e3 = a_src_g[u3 * 4 + head];
        float4 h0 = hp[u0 * 32 + lane];
        float4 h1 = hp[u1 * 32 + lane];
        float4 h2 = hp[u2 * 32 + lane];
        float4 h3 = hp[u3 * 32 + lane];
        float x0 = __expf(LEAKY(e0 + adh));
        float x1 = __expf(LEAKY(e1 + adh));
        float x2 = __expf(LEAKY(e2 + adh));
        float x3 = __expf(LEAKY(e3 + adh));
        acc.x += x0 * h0.x + x1 * h1.x + x2 * h2.x + x3 * h3.x;
        acc.y += x0 * h0.y + x1 * h1.y + x2 * h2.y + x3 * h3.y;
        acc.z += x0 * h0.z + x1 * h1.z + x2 * h2.z + x3 * h3.z;
        acc.w += x0 * h0.w + x1 * h1.w + x2 * h2.w + x3 * h3.w;
        dsum += x0 + x1 + x2 + x3;
    }
    for (; i < re; i++) {
        int u = col_g[i];
        float wv = __expf(LEAKY(a_src_g[u * 4 + head] + adh));
        float4 hu = hp[u * 32 + lane];
        acc.x += wv * hu.x;
        acc.y += wv * hu.y;
        acc.z += wv * hu.z;
        acc.w += wv * hu.w;
        dsum += wv;
    }

    float inv = 1.f / dsum;
    float4 b = ((const float4*)bias)[lane];
    float4 o;
    o.x = acc.x * inv + b.x;
    o.y = acc.y * inv + b.y;
    o.z = acc.z * inv + b.z;
    o.w = acc.w * inv + b.w;

    // ELU
    o.x = o.x > 0.f ? o.x : expm1f(o.x);
    o.y = o.y > 0.f ? o.y : expm1f(o.y);
    o.z = o.z > 0.f ? o.z : expm1f(o.z);
    o.w = o.w > 0.f ? o.w : expm1f(o.w);

    // residual
    float4 r = ((const float4*)res_g)[v * 32 + lane];
    o.x += r.x; o.y += r.y; o.z += r.z; o.w += r.w;

    // LayerNorm over 128 (warp-wide)
    float s = o.x + o.y + o.z + o.w;
#pragma unroll
    for (int off = 16; off; off >>= 1) s += __shfl_xor_sync(0xffffffffu, s, off);
    float mean = s * (1.f / 128.f);

    float cx = o.x - mean, cy = o.y - mean, cz = o.z - mean, cw = o.w - mean;
    float sq = cx * cx + cy * cy + cz * cz + cw * cw;
#pragma unroll
    for (int off = 16; off; off >>= 1) sq += __shfl_xor_sync(0xffffffffu, sq, off);
    float rinv = rsqrtf(sq * (1.f / 128.f) + 1e-5f);

    float4 g  = ((const float4*)lng)[lane];
    float4 lb = ((const float4*)lnb)[lane];
    float4 oo;
    oo.x = cx * rinv * g.x + lb.x;
    oo.y = cy * rinv * g.y + lb.y;
    oo.z = cz * rinv * g.z + lb.z;
    oo.w = cw * rinv * g.w + lb.w;

    ((float4*)out)[v * 32 + lane] = oo;
}

// ---------------- launch (fork-join; gemm is 4th submission -> ncu target) ----
extern "C" void kernel_launch(void* const* d_in, const int* in_sizes, int n_in,
                              void* d_out, int out_size)
{
    const float* x     = (const float*)d_in[0];
    const void*  ei    = d_in[1];
    const float* W     = (const float*)d_in[2];
    const float* att_s = (const float*)d_in[3];
    const float* att_d = (const float*)d_in[4];
    const float* bias  = (const float*)d_in[5];
    const float* Rw    = (const float*)d_in[6];
    const float* Rb    = (const float*)d_in[7];
    const float* lng   = (const float*)d_in[8];
    const float* lnb   = (const float*)d_in[9];

    int n = in_sizes[0] / FIN;
    int E = in_sizes[1] / 2;
    int ntiles = (n + 31) / 32;

    static cudaStream_t s2 = 0;
    static cudaEvent_t evFork = 0, evJoin = 0;
    static int inited = 0;
    int gemm_smem = (W_WORDS + X_WORDS + 384) * (int)sizeof(unsigned);  // ~43KB
    if (!inited) {
        cudaFuncSetAttribute(gemm_kernel, cudaFuncAttributeMaxDynamicSharedMemorySize, gemm_smem);
        cudaStreamCreateWithFlags(&s2, cudaStreamNonBlocking);
        cudaEventCreateWithFlags(&evFork, cudaEventDisableTiming);
        cudaEventCreateWithFlags(&evJoin, cudaEventDisableTiming);
        inited = 1;
    }

    // fork: s2 does the CSR build while stream 0 does the GEMM
    cudaEventRecord(evFork, 0);
    cudaStreamWaitEvent(s2, evFork, 0);

    extract_hist_kernel<<<(E + 255) / 256, 256, 0, s2>>>(ei, E);   // submission 1
    scan_kernel<<<1, 1024, 0, s2>>>(n);                            // submission 2
    scatter_kernel<<<(E + 255) / 256, 256, 0, s2>>>(E);            // submission 3
    cudaEventRecord(evJoin, s2);

    gemm_kernel<<<444, 256, gemm_smem>>>(x, W, Rw, Rb, att_s, att_d, n, ntiles);  // submission 4 (profiled)

    // join
    cudaStreamWaitEvent(0, evJoin, 0);
    aggregate_kernel<<<(n + 7) / 8, 256>>>(bias, lng, lnb, (float*)d_out, n);     // submission 5
}